// round 11
// baseline (speedup 1.0000x reference)
#include <cuda_runtime.h>
#include <cuda_bf16.h>
#include <math.h>
#include <stdint.h>

// Problem constants
#define BB    2
#define LL    1024
#define DD    1024
#define HH    16
#define FDIM  512
#define NLAY  4
#define NVOC  5000
#define DFF   4096
#define SS    1026          // L + 2
#define DHD   64
#define NROWS (BB*SS)       // 2052
#define OUTROWS (BB*(SS-1)) // 2050
#define NEGC  (-1000000000.0f)
#define PADS  1088          // padded S for idx tiles (17*64)

// Weight pool offsets (elements)
#define OFF_PROJ 0ULL
#define OFF_QKV  524288ULL          // stride/layer 3145728
#define OFF_WO   13107200ULL        // stride/layer 1048576
#define OFF_W13  17301504ULL        // stride/layer 8388608
#define OFF_W2   50855936ULL        // stride/layer 4194304
#define OFF_OUT  67633152ULL
#define WPOOL    72753152ULL

// ---------------------------------------------------------------------------
// Device scratch
// ---------------------------------------------------------------------------
__device__ float g_h[NROWS*DD];
__device__ float g_f[(size_t)NROWS*8192];        // W13 out + proj temp
__device__ unsigned char g_idxp[(size_t)BB*PADS*PADS];

__device__ __nv_bfloat16 g_whi[WPOOL];
__device__ __nv_bfloat16 g_wlo[WPOOL];
__device__ __nv_bfloat16 g_ahi[NROWS*DFF];       // A-operand hi
__device__ __nv_bfloat16 g_alo[NROWS*DFF];       // A-operand lo
__device__ __nv_bfloat16 g_qkvhi[(size_t)NROWS*3072];
__device__ __nv_bfloat16 g_qkvlo[(size_t)NROWS*3072];

// ---------------------------------------------------------------------------
// helpers
// ---------------------------------------------------------------------------
__device__ __forceinline__ void split1(float v, __nv_bfloat16& h, __nv_bfloat16& l) {
    h = __float2bfloat16(v);
    l = __float2bfloat16(v - __bfloat162float(h));
}
__device__ __forceinline__ uint32_t pack_bf2(__nv_bfloat16 x, __nv_bfloat16 y) {
    unsigned short a = *(unsigned short*)&x;
    unsigned short b = *(unsigned short*)&y;
    return (uint32_t)a | ((uint32_t)b << 16);
}
__device__ __forceinline__ void cp_async16(uint32_t smem_addr, const void* gptr, int src_size) {
    asm volatile("cp.async.cg.shared.global [%0], [%1], 16, %2;\n"
                 :: "r"(smem_addr), "l"(gptr), "r"(src_size));
}
__device__ __forceinline__ void cp_commit() { asm volatile("cp.async.commit_group;\n"); }
__device__ __forceinline__ void cp_wait0()  { asm volatile("cp.async.wait_group 0;\n"); }

__device__ __forceinline__ void ldsm_x4(uint32_t& r0, uint32_t& r1, uint32_t& r2, uint32_t& r3,
                                        uint32_t addr) {
    asm volatile("ldmatrix.sync.aligned.m8n8.x4.shared.b16 {%0,%1,%2,%3}, [%4];\n"
                 : "=r"(r0), "=r"(r1), "=r"(r2), "=r"(r3) : "r"(addr));
}
__device__ __forceinline__ void ldsm_x4t(uint32_t& r0, uint32_t& r1, uint32_t& r2, uint32_t& r3,
                                         uint32_t addr) {
    asm volatile("ldmatrix.sync.aligned.m8n8.x4.trans.shared.b16 {%0,%1,%2,%3}, [%4];\n"
                 : "=r"(r0), "=r"(r1), "=r"(r2), "=r"(r3) : "r"(addr));
}
__device__ __forceinline__ void mma16816(float* d,
    uint32_t a0, uint32_t a1, uint32_t a2, uint32_t a3, uint32_t b0, uint32_t b1)
{
    asm volatile("mma.sync.aligned.m16n8k16.row.col.f32.bf16.bf16.f32 "
        "{%0,%1,%2,%3}, {%4,%5,%6,%7}, {%8,%9}, {%0,%1,%2,%3};\n"
        : "+f"(d[0]), "+f"(d[1]), "+f"(d[2]), "+f"(d[3])
        : "r"(a0), "r"(a1), "r"(a2), "r"(a3), "r"(b0), "r"(b1));
}

// ---------------------------------------------------------------------------
// fp32 -> (hi, lo) split kernels
// ---------------------------------------------------------------------------
__global__ void split_k(const float* __restrict__ x, __nv_bfloat16* __restrict__ hi,
                        __nv_bfloat16* __restrict__ lo, int n4)
{
    int i = blockIdx.x * 256 + threadIdx.x;
    if (i >= n4) return;
    float4 v = ((const float4*)x)[i];
    __nv_bfloat16 h0,h1,h2,h3,l0,l1,l2,l3;
    split1(v.x,h0,l0); split1(v.y,h1,l1); split1(v.z,h2,l2); split1(v.w,h3,l3);
    __nv_bfloat162 a; a.x=h0; a.y=h1;  __nv_bfloat162 b; b.x=h2; b.y=h3;
    __nv_bfloat162 c; c.x=l0; c.y=l1;  __nv_bfloat162 d; d.x=l2; d.y=l3;
    ((__nv_bfloat162*)hi)[2*i] = a; ((__nv_bfloat162*)hi)[2*i+1] = b;
    ((__nv_bfloat162*)lo)[2*i] = c; ((__nv_bfloat162*)lo)[2*i+1] = d;
}

// pack [wq|wk|wv] along N into pool (per layer)
__global__ void pack_qkv_k(const float* __restrict__ wq, const float* __restrict__ wk,
                           const float* __restrict__ wv, int layer)
{
    const int n4 = DD * 3072 / 4;
    int i = blockIdx.x * 256 + threadIdx.x;
    if (i >= n4) return;
    size_t e = (size_t)i * 4;
    int k = (int)(e / 3072), j = (int)(e % 3072);
    const float* src;
    if (j < 1024)      src = wq + (size_t)layer*DD*DD + (size_t)k*DD + j;
    else if (j < 2048) src = wk + (size_t)layer*DD*DD + (size_t)k*DD + (j - 1024);
    else               src = wv + (size_t)layer*DD*DD + (size_t)k*DD + (j - 2048);
    float4 v = *(const float4*)src;
    size_t off = OFF_QKV + (size_t)layer * 3145728ULL + e;
    __nv_bfloat16 h0,h1,h2,h3,l0,l1,l2,l3;
    split1(v.x,h0,l0); split1(v.y,h1,l1); split1(v.z,h2,l2); split1(v.w,h3,l3);
    g_whi[off]=h0; g_whi[off+1]=h1; g_whi[off+2]=h2; g_whi[off+3]=h3;
    g_wlo[off]=l0; g_wlo[off+1]=l1; g_wlo[off+2]=l2; g_wlo[off+3]=l3;
}

// pack [w1|w3] along N into pool (per layer)
__global__ void pack_w13_k(const float* __restrict__ w1, const float* __restrict__ w3,
                           int layer)
{
    const int n4 = DD * 8192 / 4;
    int i = blockIdx.x * 256 + threadIdx.x;
    if (i >= n4) return;
    size_t e = (size_t)i * 4;
    int k = (int)(e / 8192), j = (int)(e % 8192);
    const float* src;
    if (j < 4096) src = w1 + (size_t)layer*DD*DFF + (size_t)k*DFF + j;
    else          src = w3 + (size_t)layer*DD*DFF + (size_t)k*DFF + (j - 4096);
    float4 v = *(const float4*)src;
    size_t off = OFF_W13 + (size_t)layer * 8388608ULL + e;
    __nv_bfloat16 h0,h1,h2,h3,l0,l1,l2,l3;
    split1(v.x,h0,l0); split1(v.y,h1,l1); split1(v.z,h2,l2); split1(v.w,h3,l3);
    g_whi[off]=h0; g_whi[off+1]=h1; g_whi[off+2]=h2; g_whi[off+3]=h3;
    g_wlo[off]=l0; g_wlo[off+1]=l1; g_wlo[off+2]=l2; g_wlo[off+3]=l3;
}

// ---------------------------------------------------------------------------
// bf16x3 GEMM core (fp32 epilogue): C (+)= Ahi@Bhi + Alo@Bhi + Ahi@Blo (+bias)
// ---------------------------------------------------------------------------
__global__ void __launch_bounds__(256) bf3gemm_k(
    const __nv_bfloat16* __restrict__ Ahi, const __nv_bfloat16* __restrict__ Alo,
    const __nv_bfloat16* __restrict__ Bhi, const __nv_bfloat16* __restrict__ Blo,
    const float* __restrict__ bias, float* __restrict__ C,
    int M, int N, int K, int accumulate)
{
    __shared__ __align__(16) __nv_bfloat16 As[2][128][40];
    __shared__ __align__(16) __nv_bfloat16 Bs[2][32][136];

    const int tid  = threadIdx.x;
    const int lane = tid & 31;
    const int wid  = tid >> 5;
    const int wm   = (wid >> 2) * 64;
    const int wn   = (wid & 3) * 32;
    const int brow = blockIdx.y * 128;
    const int bcol = blockIdx.x * 128;

    float acc[4][4][4];
#pragma unroll
    for (int mi = 0; mi < 4; mi++)
#pragma unroll
        for (int ni = 0; ni < 4; ni++)
#pragma unroll
            for (int r = 0; r < 4; r++) acc[mi][ni][r] = 0.f;

    const uint32_t As_addr = (uint32_t)__cvta_generic_to_shared(&As[0][0][0]);
    const uint32_t Bs_addr = (uint32_t)__cvta_generic_to_shared(&Bs[0][0][0]);

    const int kchunks = K >> 5;
    const int niters  = 3 * kchunks;

    auto load_tiles = [&](int b, int t) {
        const int phase = t / kchunks;
        const int k0 = (t - phase * kchunks) << 5;
        const __nv_bfloat16* Asrc = (phase == 1) ? Alo : Ahi;
        const __nv_bfloat16* Bsrc = (phase == 2) ? Blo : Bhi;
#pragma unroll
        for (int c = 0; c < 2; c++) {
            const int cid = tid + (c << 8);
            const int row = cid >> 2, chk = cid & 3;
            const int grow = brow + row;
            const __nv_bfloat16* src = Asrc + (size_t)grow * K + k0 + chk * 8;
            int sz = 16;
            if (grow >= M) { sz = 0; src = Asrc; }
            cp_async16(As_addr + (uint32_t)(((b * 128 + row) * 40 + chk * 8) << 1), src, sz);
        }
#pragma unroll
        for (int c = 0; c < 2; c++) {
            const int cid = tid + (c << 8);
            const int row = cid >> 4, chk = cid & 15;
            const int gcol = bcol + chk * 8;
            const __nv_bfloat16* src = Bsrc + (size_t)(k0 + row) * N + gcol;
            int sz = 16;
            if (gcol + 8 > N) { sz = 0; src = Bsrc; }
            cp_async16(Bs_addr + (uint32_t)(((b * 32 + row) * 136 + chk * 8) << 1), src, sz);
        }
    };

    int buf = 0;
    load_tiles(0, 0);
    cp_commit();

    const int a_row = (lane & 15);
    const int a_col = (lane >> 4) * 8;

    for (int t = 0; t < niters; ++t) {
        cp_wait0();
        __syncthreads();
        if (t + 1 < niters) { load_tiles(buf ^ 1, t + 1); cp_commit(); }

#pragma unroll
        for (int ks = 0; ks < 32; ks += 16) {
            uint32_t afrag[4][4];
#pragma unroll
            for (int mi = 0; mi < 4; mi++) {
                const uint32_t addr = As_addr +
                    (uint32_t)(((buf * 128 + wm + mi * 16 + a_row) * 40 + ks + a_col) << 1);
                ldsm_x4(afrag[mi][0], afrag[mi][1], afrag[mi][2], afrag[mi][3], addr);
            }
            uint32_t bfrag[4][2];
#pragma unroll
            for (int pr = 0; pr < 2; pr++) {
                const uint32_t addr = Bs_addr +
                    (uint32_t)(((buf * 32 + ks + a_row) * 136 + wn + pr * 16 + a_col) << 1);
                ldsm_x4t(bfrag[pr*2][0], bfrag[pr*2][1], bfrag[pr*2+1][0], bfrag[pr*2+1][1], addr);
            }
#pragma unroll
            for (int mi = 0; mi < 4; mi++)
#pragma unroll
                for (int ni = 0; ni < 4; ni++)
                    mma16816(acc[mi][ni],
                             afrag[mi][0], afrag[mi][1], afrag[mi][2], afrag[mi][3],
                             bfrag[ni][0], bfrag[ni][1]);
        }
        __syncthreads();
        buf ^= 1;
    }

#pragma unroll
    for (int mi = 0; mi < 4; mi++) {
        const int r0 = brow + wm + mi * 16 + (lane >> 2);
#pragma unroll
        for (int ni = 0; ni < 4; ni++) {
            const int c0 = bcol + wn + ni * 8 + (lane & 3) * 2;
#pragma unroll
            for (int half = 0; half < 2; half++) {
                const int r = r0 + half * 8;
                if (r >= M) continue;
#pragma unroll
                for (int cc = 0; cc < 2; cc++) {
                    const int c = c0 + cc;
                    if (c >= N) continue;
                    float v = acc[mi][ni][half * 2 + cc];
                    if (bias) v += bias[c];
                    if (accumulate) v += C[(size_t)r * N + c];
                    C[(size_t)r * N + c] = v;
                }
            }
        }
    }
}

// Same GEMM, epilogue writes bf16 hi/lo (for QKV)
__global__ void __launch_bounds__(256) bf3gemm_split_k(
    const __nv_bfloat16* __restrict__ Ahi, const __nv_bfloat16* __restrict__ Alo,
    const __nv_bfloat16* __restrict__ Bhi, const __nv_bfloat16* __restrict__ Blo,
    __nv_bfloat16* __restrict__ Chi, __nv_bfloat16* __restrict__ Clo,
    int M, int N, int K)
{
    __shared__ __align__(16) __nv_bfloat16 As[2][128][40];
    __shared__ __align__(16) __nv_bfloat16 Bs[2][32][136];

    const int tid  = threadIdx.x;
    const int lane = tid & 31;
    const int wid  = tid >> 5;
    const int wm   = (wid >> 2) * 64;
    const int wn   = (wid & 3) * 32;
    const int brow = blockIdx.y * 128;
    const int bcol = blockIdx.x * 128;

    float acc[4][4][4];
#pragma unroll
    for (int mi = 0; mi < 4; mi++)
#pragma unroll
        for (int ni = 0; ni < 4; ni++)
#pragma unroll
            for (int r = 0; r < 4; r++) acc[mi][ni][r] = 0.f;

    const uint32_t As_addr = (uint32_t)__cvta_generic_to_shared(&As[0][0][0]);
    const uint32_t Bs_addr = (uint32_t)__cvta_generic_to_shared(&Bs[0][0][0]);

    const int kchunks = K >> 5;
    const int niters  = 3 * kchunks;

    auto load_tiles = [&](int b, int t) {
        const int phase = t / kchunks;
        const int k0 = (t - phase * kchunks) << 5;
        const __nv_bfloat16* Asrc = (phase == 1) ? Alo : Ahi;
        const __nv_bfloat16* Bsrc = (phase == 2) ? Blo : Bhi;
#pragma unroll
        for (int c = 0; c < 2; c++) {
            const int cid = tid + (c << 8);
            const int row = cid >> 2, chk = cid & 3;
            const int grow = brow + row;
            const __nv_bfloat16* src = Asrc + (size_t)grow * K + k0 + chk * 8;
            int sz = 16;
            if (grow >= M) { sz = 0; src = Asrc; }
            cp_async16(As_addr + (uint32_t)(((b * 128 + row) * 40 + chk * 8) << 1), src, sz);
        }
#pragma unroll
        for (int c = 0; c < 2; c++) {
            const int cid = tid + (c << 8);
            const int row = cid >> 4, chk = cid & 15;
            const int gcol = bcol + chk * 8;
            const __nv_bfloat16* src = Bsrc + (size_t)(k0 + row) * N + gcol;
            int sz = 16;
            if (gcol + 8 > N) { sz = 0; src = Bsrc; }
            cp_async16(Bs_addr + (uint32_t)(((b * 32 + row) * 136 + chk * 8) << 1), src, sz);
        }
    };

    int buf = 0;
    load_tiles(0, 0);
    cp_commit();

    const int a_row = (lane & 15);
    const int a_col = (lane >> 4) * 8;

    for (int t = 0; t < niters; ++t) {
        cp_wait0();
        __syncthreads();
        if (t + 1 < niters) { load_tiles(buf ^ 1, t + 1); cp_commit(); }

#pragma unroll
        for (int ks = 0; ks < 32; ks += 16) {
            uint32_t afrag[4][4];
#pragma unroll
            for (int mi = 0; mi < 4; mi++) {
                const uint32_t addr = As_addr +
                    (uint32_t)(((buf * 128 + wm + mi * 16 + a_row) * 40 + ks + a_col) << 1);
                ldsm_x4(afrag[mi][0], afrag[mi][1], afrag[mi][2], afrag[mi][3], addr);
            }
            uint32_t bfrag[4][2];
#pragma unroll
            for (int pr = 0; pr < 2; pr++) {
                const uint32_t addr = Bs_addr +
                    (uint32_t)(((buf * 32 + ks + a_row) * 136 + wn + pr * 16 + a_col) << 1);
                ldsm_x4t(bfrag[pr*2][0], bfrag[pr*2][1], bfrag[pr*2+1][0], bfrag[pr*2+1][1], addr);
            }
#pragma unroll
            for (int mi = 0; mi < 4; mi++)
#pragma unroll
                for (int ni = 0; ni < 4; ni++)
                    mma16816(acc[mi][ni],
                             afrag[mi][0], afrag[mi][1], afrag[mi][2], afrag[mi][3],
                             bfrag[ni][0], bfrag[ni][1]);
        }
        __syncthreads();
        buf ^= 1;
    }

#pragma unroll
    for (int mi = 0; mi < 4; mi++) {
        const int r0 = brow + wm + mi * 16 + (lane >> 2);
#pragma unroll
        for (int ni = 0; ni < 4; ni++) {
            const int c0 = bcol + wn + ni * 8 + (lane & 3) * 2;
#pragma unroll
            for (int half = 0; half < 2; half++) {
                const int r = r0 + half * 8;
                if (r >= M) continue;
#pragma unroll
                for (int cc = 0; cc < 2; cc++) {
                    const int c = c0 + cc;
                    if (c >= N) continue;
                    __nv_bfloat16 hv, lv;
                    split1(acc[mi][ni][half * 2 + cc], hv, lv);
                    Chi[(size_t)r * N + c] = hv;
                    Clo[(size_t)r * N + c] = lv;
                }
            }
        }
    }
}

// ---------------------------------------------------------------------------
// Fused flash attention. block = 128 thr (4 warps, 16 q-rows each).
// grid = (17 qtiles, B*H). Inputs: packed QKV hi/lo. Output att hi/lo.
// ---------------------------------------------------------------------------
__global__ void __launch_bounds__(128) flash_k(
    const __nv_bfloat16* __restrict__ qkvhi, const __nv_bfloat16* __restrict__ qkvlo,
    const float* __restrict__ spd_emb, const int* __restrict__ mask_len,
    __nv_bfloat16* __restrict__ ohi, __nv_bfloat16* __restrict__ olo)
{
    extern __shared__ __align__(16) char sm[];
    __nv_bfloat16* sKhi = (__nv_bfloat16*)sm;        // [64][72]
    __nv_bfloat16* sKlo = sKhi + 64*72;
    __nv_bfloat16* sVhi = sKlo + 64*72;
    __nv_bfloat16* sVlo = sVhi + 64*72;
    __nv_bfloat16* sQhi = sVlo + 64*72;
    __nv_bfloat16* sQlo = sQhi + 64*72;
    unsigned char* sIdx = (unsigned char*)(sQlo + 64*72); // [64][64]
    float* sB = (float*)(sIdx + 64*64);              // [32]

    const int tid = threadIdx.x, lane = tid & 31, wid = tid >> 5;
    const int wr = wid * 16;
    const int bh = blockIdx.y, b = bh >> 4, h = bh & 15;
    const int q0 = blockIdx.x * 64;
    const int vlen = mask_len[b] + 2;

    if (tid < 32) sB[tid] = spd_emb[tid * HH + h];

    const uint32_t sKhi_a = (uint32_t)__cvta_generic_to_shared(sKhi);
    const uint32_t sKlo_a = (uint32_t)__cvta_generic_to_shared(sKlo);
    const uint32_t sVhi_a = (uint32_t)__cvta_generic_to_shared(sVhi);
    const uint32_t sVlo_a = (uint32_t)__cvta_generic_to_shared(sVlo);
    const uint32_t sQhi_a = (uint32_t)__cvta_generic_to_shared(sQhi);
    const uint32_t sQlo_a = (uint32_t)__cvta_generic_to_shared(sQlo);
    const uint32_t sIdx_a = (uint32_t)__cvta_generic_to_shared(sIdx);

    // Load Q tile (hi/lo)
#pragma unroll
    for (int c = 0; c < 4; c++) {
        const int cid = tid + c * 128;
        const int row = cid >> 3, chk = cid & 7;
        const int gq = q0 + row;
        size_t base = ((size_t)(b * SS + gq)) * 3072 + h * 64 + chk * 8;
        int sz = (gq < SS) ? 16 : 0;
        const __nv_bfloat16* sh = (gq < SS) ? qkvhi + base : qkvhi;
        const __nv_bfloat16* sl = (gq < SS) ? qkvlo + base : qkvlo;
        cp_async16(sQhi_a + (uint32_t)((row * 72 + chk * 8) << 1), sh, sz);
        cp_async16(sQlo_a + (uint32_t)((row * 72 + chk * 8) << 1), sl, sz);
    }
    cp_commit(); cp_wait0(); __syncthreads();

    uint32_t qfh[4][4], qfl[4][4];
#pragma unroll
    for (int c = 0; c < 4; c++) {
        uint32_t off = (uint32_t)((((wr + (lane & 15)) * 72) + c * 16 + ((lane >> 4) << 3)) << 1);
        ldsm_x4(qfh[c][0], qfh[c][1], qfh[c][2], qfh[c][3], sQhi_a + off);
        ldsm_x4(qfl[c][0], qfl[c][1], qfl[c][2], qfl[c][3], sQlo_a + off);
    }

    float m_a = -1e30f, m_b = -1e30f, l_a = 0.f, l_b = 0.f;
    float O[8][4];
#pragma unroll
    for (int nt = 0; nt < 8; nt++)
#pragma unroll
        for (int j = 0; j < 4; j++) O[nt][j] = 0.f;

    const int qa_l = wr + (lane >> 2);
    const int qb_l = qa_l + 8;
    const int qga = q0 + qa_l, qgb = q0 + qb_l;
    const float mka = (qga < vlen) ? 0.f : NEGC;
    const float mkb = (qgb < vlen) ? 0.f : NEGC;
    const int kc_base = (lane & 3) * 2;

    for (int kt = 0; kt < 17; kt++) {
        const int k0 = kt * 64;
        __syncthreads();
        // load K/V hi/lo tiles + idx tile
#pragma unroll
        for (int c = 0; c < 4; c++) {
            const int cid = tid + c * 128;
            const int row = cid >> 3, chk = cid & 7;
            const int gk = k0 + row;
            size_t base = ((size_t)(b * SS + gk)) * 3072 + h * 64 + chk * 8;
            int sz = (gk < SS) ? 16 : 0;
            const __nv_bfloat16* kh = (gk < SS) ? qkvhi + base + 1024 : qkvhi;
            const __nv_bfloat16* kl = (gk < SS) ? qkvlo + base + 1024 : qkvlo;
            const __nv_bfloat16* vh = (gk < SS) ? qkvhi + base + 2048 : qkvhi;
            const __nv_bfloat16* vl = (gk < SS) ? qkvlo + base + 2048 : qkvlo;
            uint32_t doff = (uint32_t)((row * 72 + chk * 8) << 1);
            cp_async16(sKhi_a + doff, kh, sz);
            cp_async16(sKlo_a + doff, kl, sz);
            cp_async16(sVhi_a + doff, vh, sz);
            cp_async16(sVlo_a + doff, vl, sz);
        }
#pragma unroll
        for (int c = 0; c < 2; c++) {
            const int cid = tid + c * 128;
            const int row = cid >> 2, chk = cid & 3;
            const unsigned char* src = g_idxp + ((size_t)b * PADS + q0 + row) * PADS + k0 + chk * 16;
            cp_async16(sIdx_a + (uint32_t)(row * 64 + chk * 16), src, 16);
        }
        cp_commit(); cp_wait0(); __syncthreads();

        // S = Q K^T (3-term)
        float s[8][4];
#pragma unroll
        for (int nt = 0; nt < 8; nt++)
#pragma unroll
            for (int j = 0; j < 4; j++) s[nt][j] = 0.f;

#pragma unroll
        for (int c = 0; c < 4; c++) {
#pragma unroll
            for (int p = 0; p < 4; p++) {
                uint32_t r0, r1, r2, r3;
                uint32_t off = (uint32_t)((((p * 16 + (lane & 15)) * 72) + c * 16 + ((lane >> 4) << 3)) << 1);
                ldsm_x4(r0, r1, r2, r3, sKhi_a + off);
                mma16816(s[2*p],   qfh[c][0], qfh[c][1], qfh[c][2], qfh[c][3], r0, r2);
                mma16816(s[2*p+1], qfh[c][0], qfh[c][1], qfh[c][2], qfh[c][3], r1, r3);
                mma16816(s[2*p],   qfl[c][0], qfl[c][1], qfl[c][2], qfl[c][3], r0, r2);
                mma16816(s[2*p+1], qfl[c][0], qfl[c][1], qfl[c][2], qfl[c][3], r1, r3);
                ldsm_x4(r0, r1, r2, r3, sKlo_a + off);
                mma16816(s[2*p],   qfh[c][0], qfh[c][1], qfh[c][2], qfh[c][3], r0, r2);
                mma16816(s[2*p+1], qfh[c][0], qfh[c][1], qfh[c][2], qfh[c][3], r1, r3);
            }
        }

        // scale + bias + mask
        float pmax_a = -1e30f, pmax_b = -1e30f;
#pragma unroll
        for (int nt = 0; nt < 8; nt++) {
            const int colbase = nt * 8 + kc_base;
#pragma unroll
            for (int j = 0; j < 4; j++) {
                const int kc = colbase + (j & 1);
                const int qr = (j < 2) ? qa_l : qb_l;
                const float bias = sB[sIdx[qr * 64 + kc]];
                float v = (s[nt][j] * 0.125f + bias) + ((j < 2) ? mka : mkb);
                if (k0 + kc >= SS) v = -1e30f;
                s[nt][j] = v;
                if (j < 2) pmax_a = fmaxf(pmax_a, v);
                else       pmax_b = fmaxf(pmax_b, v);
            }
        }
        pmax_a = fmaxf(pmax_a, __shfl_xor_sync(0xffffffff, pmax_a, 1));
        pmax_a = fmaxf(pmax_a, __shfl_xor_sync(0xffffffff, pmax_a, 2));
        pmax_b = fmaxf(pmax_b, __shfl_xor_sync(0xffffffff, pmax_b, 1));
        pmax_b = fmaxf(pmax_b, __shfl_xor_sync(0xffffffff, pmax_b, 2));

        const float mna = fmaxf(m_a, pmax_a), mnb = fmaxf(m_b, pmax_b);
        const float ca = __expf(m_a - mna), cb = __expf(m_b - mnb);
        float suma = 0.f, sumb = 0.f;
#pragma unroll
        for (int nt = 0; nt < 8; nt++) {
#pragma unroll
            for (int j = 0; j < 4; j++) {
                float e = __expf(s[nt][j] - ((j < 2) ? mna : mnb));
                s[nt][j] = e;
                if (j < 2) suma += e; else sumb += e;
            }
        }
        suma += __shfl_xor_sync(0xffffffff, suma, 1);
        suma += __shfl_xor_sync(0xffffffff, suma, 2);
        sumb += __shfl_xor_sync(0xffffffff, sumb, 1);
        sumb += __shfl_xor_sync(0xffffffff, sumb, 2);
        l_a = l_a * ca + suma; m_a = mna;
        l_b = l_b * cb + sumb; m_b = mnb;
#pragma unroll
        for (int nt = 0; nt < 8; nt++) {
            O[nt][0] *= ca; O[nt][1] *= ca;
            O[nt][2] *= cb; O[nt][3] *= cb;
        }

        // PV (3-term): P from accumulators -> a-frags
#pragma unroll
        for (int c = 0; c < 4; c++) {
            __nv_bfloat16 h00,h01,h02,h03,h10,h11,h12,h13;
            __nv_bfloat16 l00,l01,l02,l03,l10,l11,l12,l13;
            split1(s[2*c][0], h00, l00); split1(s[2*c][1], h01, l01);
            split1(s[2*c][2], h02, l02); split1(s[2*c][3], h03, l03);
            split1(s[2*c+1][0], h10, l10); split1(s[2*c+1][1], h11, l11);
            split1(s[2*c+1][2], h12, l12); split1(s[2*c+1][3], h13, l13);
            uint32_t pa0 = pack_bf2(h00, h01), pa1 = pack_bf2(h02, h03);
            uint32_t pa2 = pack_bf2(h10, h11), pa3 = pack_bf2(h12, h13);
            uint32_t pl0 = pack_bf2(l00, l01), pl1 = pack_bf2(l02, l03);
            uint32_t pl2 = pack_bf2(l10, l11), pl3 = pack_bf2(l12, l13);
#pragma unroll
            for (int dp = 0; dp < 4; dp++) {
                uint32_t r0, r1, r2, r3;
                uint32_t off = (uint32_t)((((c * 16 + (lane & 15)) * 72) + dp * 16 + ((lane >> 4) << 3)) << 1);
                ldsm_x4t(r0, r1, r2, r3, sVhi_a + off);
                mma16816(O[2*dp],   pa0, pa1, pa2, pa3, r0, r1);
                mma16816(O[2*dp+1], pa0, pa1, pa2, pa3, r2, r3);
                mma16816(O[2*dp],   pl0, pl1, pl2, pl3, r0, r1);
                mma16816(O[2*dp+1], pl0, pl1, pl2, pl3, r2, r3);
                ldsm_x4t(r0, r1, r2, r3, sVlo_a + off);
                mma16816(O[2*dp],   pa0, pa1, pa2, pa3, r0, r1);
                mma16816(O[2*dp+1], pa0, pa1, pa2, pa3, r2, r3);
            }
        }
    }

    // epilogue: normalize + split-store
    const float ia = 1.f / l_a, ib = 1.f / l_b;
#pragma unroll
    for (int nt = 0; nt < 8; nt++) {
#pragma unroll
        for (int j = 0; j < 4; j++) {
            const int q = (j < 2) ? qga : qgb;
            if (q >= SS) continue;
            const int d = h * 64 + nt * 8 + kc_base + (j & 1);
            float v = O[nt][j] * ((j < 2) ? ia : ib);
            __nv_bfloat16 hv, lv;
            split1(v, hv, lv);
            const size_t off = ((size_t)(b * SS + q)) * DD + d;
            ohi[off] = hv; olo[off] = lv;
        }
    }
}

// ---------------------------------------------------------------------------
// Embedding assembly
// ---------------------------------------------------------------------------
__global__ void embed_k(
    const float* __restrict__ proj, const float* __restrict__ graph,
    const float* __restrict__ sos,  const float* __restrict__ node_emb,
    const float* __restrict__ type_emb, const float* __restrict__ pos_emb,
    const int*   __restrict__ sub)
{
    const int s = blockIdx.x;
    const int b = blockIdx.y;
    const int d = threadIdx.x * 4;

    float4 pos = *(const float4*)(pos_emb + (size_t)s * DD + d);
    float4 o;
    if (s == 0) {
        float4 g = *(const float4*)(graph + (size_t)b * DD + d);
        float4 t1 = *(const float4*)(type_emb + DD + d);
        o.x = g.x + t1.x + pos.x; o.y = g.y + t1.y + pos.y;
        o.z = g.z + t1.z + pos.z; o.w = g.w + t1.w + pos.w;
    } else {
        const int t = s - 1;
        float4 base;
        int nid;
        if (t == 0) {
            base = *(const float4*)(sos + d);
            nid = 0;
        } else {
            base = *(const float4*)(proj + ((size_t)b * LL + (t-1)) * DD + d);
            nid = sub[b * LL + (t-1)];
        }
        float4 ne = *(const float4*)(node_emb + (size_t)nid * DD + d);
        float4 t0 = *(const float4*)(type_emb + d);
        o.x = base.x + ne.x + t0.x + pos.x;
        o.y = base.y + ne.y + t0.y + pos.y;
        o.z = base.z + ne.z + t0.z + pos.z;
        o.w = base.w + ne.w + t0.w + pos.w;
    }
    *(float4*)(g_h + ((size_t)b * SS + s) * DD + d) = o;
}

// ---------------------------------------------------------------------------
// spd bias index precompute into padded [PADS][PADS] (OOB -> 31)
// ---------------------------------------------------------------------------
__global__ void spdidx_k(const int* __restrict__ spd)
{
    const int qk = blockIdx.x * 256 + threadIdx.x;
    const int b  = blockIdx.y;
    if (qk >= PADS * PADS) return;
    const int q = qk / PADS, k = qk % PADS;
    int idx;
    if (q >= SS || k >= SS) idx = 31;
    else if (q >= 2 && k >= 2) {
        idx = spd[((size_t)b * LL + (q-2)) * LL + (k-2)];
        if (idx < 0) idx = 0;
        if (idx > 31) idx = 31;
    } else {
        idx = (q == k) ? 0 : 31;
    }
    g_idxp[(size_t)b * PADS * PADS + qk] = (unsigned char)idx;
}

// ---------------------------------------------------------------------------
// RMSNorm -> bf16 hi/lo
// ---------------------------------------------------------------------------
__device__ __forceinline__ float block_reduce_sum(float v, float* red) {
    const int tid = threadIdx.x;
    red[tid] = v; __syncthreads();
    for (int s = 128; s > 0; s >>= 1) {
        if (tid < s) red[tid] += red[tid + s];
        __syncthreads();
    }
    float r = red[0]; __syncthreads();
    return r;
}

__global__ void rmsnorm_bf_k(const float* __restrict__ h, const float* __restrict__ w,
                             __nv_bfloat16* __restrict__ hi, __nv_bfloat16* __restrict__ lo)
{
    __shared__ float red[256];
    const int row = blockIdx.x;
    const int tid = threadIdx.x;
    const float* x = h + (size_t)row * DD;
    float4 xv = *(const float4*)(x + tid * 4);
    float ss = xv.x*xv.x + xv.y*xv.y + xv.z*xv.z + xv.w*xv.w;
    float tot = block_reduce_sum(ss, red);
    float inv = rsqrtf(tot / (float)DD + 1e-6f);
    float4 wv = *(const float4*)(w + tid * 4);
    float o0 = xv.x*inv*wv.x, o1 = xv.y*inv*wv.y, o2 = xv.z*inv*wv.z, o3 = xv.w*inv*wv.w;
    __nv_bfloat16 h0,h1,h2,h3,l0,l1,l2,l3;
    split1(o0,h0,l0); split1(o1,h1,l1); split1(o2,h2,l2); split1(o3,h3,l3);
    const size_t base = (size_t)row * DD + tid * 4;
    hi[base+0]=h0; hi[base+1]=h1; hi[base+2]=h2; hi[base+3]=h3;
    lo[base+0]=l0; lo[base+1]=l1; lo[base+2]=l2; lo[base+3]=l3;
}

__global__ void rmsnorm_final_bf_k(const float* __restrict__ h, const float* __restrict__ w,
                                   __nv_bfloat16* __restrict__ hi, __nv_bfloat16* __restrict__ lo)
{
    __shared__ float red[256];
    const int r = blockIdx.x;
    const int b = r / (SS - 1);
    const int t = r % (SS - 1);
    const int src = b * SS + 1 + t;
    const int tid = threadIdx.x;
    const float* x = h + (size_t)src * DD;
    float4 xv = *(const float4*)(x + tid * 4);
    float ss = xv.x*xv.x + xv.y*xv.y + xv.z*xv.z + xv.w*xv.w;
    float tot = block_reduce_sum(ss, red);
    float inv = rsqrtf(tot / (float)DD + 1e-6f);
    float4 wv = *(const float4*)(w + tid * 4);
    float o0 = xv.x*inv*wv.x, o1 = xv.y*inv*wv.y, o2 = xv.z*inv*wv.z, o3 = xv.w*inv*wv.w;
    __nv_bfloat16 h0,h1,h2,h3,l0,l1,l2,l3;
    split1(o0,h0,l0); split1(o1,h1,l1); split1(o2,h2,l2); split1(o3,h3,l3);
    const size_t base = (size_t)r * DD + tid * 4;
    hi[base+0]=h0; hi[base+1]=h1; hi[base+2]=h2; hi[base+3]=h3;
    lo[base+0]=l0; lo[base+1]=l1; lo[base+2]=l2; lo[base+3]=l3;
}

// ---------------------------------------------------------------------------
// SwiGLU gate from packed g_f [NROWS][8192] -> bf16 hi/lo [NROWS][4096]
// ---------------------------------------------------------------------------
__global__ void silu_split_k(const float* __restrict__ f,
                             __nv_bfloat16* __restrict__ hi, __nv_bfloat16* __restrict__ lo,
                             int n4)
{
    int i = blockIdx.x * 256 + threadIdx.x;
    if (i >= n4) return;
    size_t e = (size_t)i * 4;
    int r = (int)(e >> 12);          // /4096
    int c = (int)(e & 4095);
    float4 a = *(const float4*)(f + (size_t)r * 8192 + c);
    float4 g = *(const float4*)(f + (size_t)r * 8192 + 4096 + c);
    float o0 = (a.x / (1.f + __expf(-a.x))) * g.x;
    float o1 = (a.y / (1.f + __expf(-a.y))) * g.y;
    float o2 = (a.z / (1.f + __expf(-a.z))) * g.z;
    float o3 = (a.w / (1.f + __expf(-a.w))) * g.w;
    __nv_bfloat16 h0,h1,h2,h3,l0,l1,l2,l3;
    split1(o0,h0,l0); split1(o1,h1,l1); split1(o2,h2,l2); split1(o3,h3,l3);
    hi[e+0]=h0; hi[e+1]=h1; hi[e+2]=h2; hi[e+3]=h3;
    lo[e+0]=l0; lo[e+1]=l1; lo[e+2]=l2; lo[e+3]=l3;
}

// ---------------------------------------------------------------------------
// Host orchestration
// ---------------------------------------------------------------------------
static __nv_bfloat16 *p_whi, *p_wlo, *p_ahi, *p_alo, *p_qkvhi, *p_qkvlo;

static inline void run_bf3(const __nv_bfloat16* Bhi, const __nv_bfloat16* Blo,
                           const float* bias, float* C, int M, int N, int K, int acc)
{
    dim3 grid((N + 127) / 128, (M + 127) / 128);
    bf3gemm_k<<<grid, 256>>>(p_ahi, p_alo, Bhi, Blo, bias, C, M, N, K, acc);
}

extern "C" void kernel_launch(void* const* d_in, const int* in_sizes, int n_in,
                              void* d_out, int out_size)
{
    const float* graph_features = (const float*)d_in[0];
    const float* input_features = (const float*)d_in[1];
    const float* proj_W         = (const float*)d_in[2];
    const float* proj_b         = (const float*)d_in[3];
    const float* sos_token      = (const float*)d_in[4];
    const float* node_emb       = (const float*)d_in[5];
    const float* type_emb       = (const float*)d_in[6];
    const float* pos_emb        = (const float*)d_in[7];
    const float* spd_emb        = (const float*)d_in[8];
    const float* attn_norm_w    = (const float*)d_in[9];
    const float* wq             = (const float*)d_in[10];
    const float* wk             = (const float*)d_in[11];
    const float* wv             = (const float*)d_in[12];
    const float* wo             = (const float*)d_in[13];
    const float* ffn_norm_w     = (const float*)d_in[14];
    const float* w1             = (const float*)d_in[15];
    const float* w2             = (const float*)d_in[16];
    const float* w3             = (const float*)d_in[17];
    const float* final_norm_w   = (const float*)d_in[18];
    const float* out_W          = (const float*)d_in[19];
    const float* out_b          = (const float*)d_in[20];
    const int*   subnode_ids    = (const int*)d_in[21];
    const int*   token_mask_len = (const int*)d_in[22];
    const int*   spd_indices    = (const int*)d_in[23];

    float *p_h, *p_f;
    cudaGetSymbolAddress((void**)&p_h,   g_h);
    cudaGetSymbolAddress((void**)&p_f,   g_f);
    cudaGetSymbolAddress((void**)&p_whi, g_whi);
    cudaGetSymbolAddress((void**)&p_wlo, g_wlo);
    cudaGetSymbolAddress((void**)&p_ahi, g_ahi);
    cudaGetSymbolAddress((void**)&p_alo, g_alo);
    cudaGetSymbolAddress((void**)&p_qkvhi, g_qkvhi);
    cudaGetSymbolAddress((void**)&p_qkvlo, g_qkvlo);

    cudaFuncSetAttribute(flash_k, cudaFuncAttributeMaxDynamicSharedMemorySize, 59520);

    // 0) Weight splits/packs + spd idx
    auto splitw = [&](const float* src, size_t off, size_t count) {
        split_k<<<(unsigned)((count/4 + 255) / 256), 256>>>(src, p_whi + off, p_wlo + off,
                                                            (int)(count/4));
    };
    splitw(proj_W, OFF_PROJ, (size_t)FDIM*DD);
    for (int i = 0; i < NLAY; i++) {
        pack_qkv_k<<<(DD*3072/4 + 255)/256, 256>>>(wq, wk, wv, i);
        splitw(wo + (size_t)i*DD*DD, OFF_WO + (size_t)i*DD*DD, (size_t)DD*DD);
        pack_w13_k<<<(DD*8192/4 + 255)/256, 256>>>(w1, w3, i);
        splitw(w2 + (size_t)i*DFF*DD, OFF_W2 + (size_t)i*DFF*DD, (size_t)DFF*DD);
    }
    splitw(out_W, OFF_OUT, (size_t)DD*NVOC);
    spdidx_k<<<dim3((PADS*PADS + 255) / 256, BB), 256>>>(spd_indices);

    // 1) Input projection -> g_f (temp, row stride 1024)
    split_k<<<(unsigned)(((size_t)BB*LL*FDIM/4 + 255) / 256), 256>>>(
        input_features, p_ahi, p_alo, (int)((size_t)BB*LL*FDIM/4));
    run_bf3(p_whi + OFF_PROJ, p_wlo + OFF_PROJ, proj_b, p_f, BB*LL, DD, FDIM, 0);

    // 2) Embedding assembly -> g_h
    embed_k<<<dim3(SS, BB), 256>>>(p_f, graph_features, sos_token,
                                   node_emb, type_emb, pos_emb, subnode_ids);

    // 3) Transformer layers
    for (int i = 0; i < NLAY; i++) {
        const size_t qkvoff = OFF_QKV + (size_t)i * 3145728ULL;
        const size_t wooff  = OFF_WO  + (size_t)i * 1048576ULL;
        const size_t w13off = OFF_W13 + (size_t)i * 8388608ULL;
        const size_t w2off  = OFF_W2  + (size_t)i * 4194304ULL;

        rmsnorm_bf_k<<<NROWS, 256>>>(p_h, attn_norm_w + i*DD, p_ahi, p_alo);
        {
            dim3 grid(3072/128, (NROWS + 127)/128);
            bf3gemm_split_k<<<grid, 256>>>(p_ahi, p_alo, p_whi + qkvoff, p_wlo + qkvoff,
                                           p_qkvhi, p_qkvlo, NROWS, 3072, DD);
        }
        flash_k<<<dim3(17, BB*HH), 128, 59520>>>(p_qkvhi, p_qkvlo, spd_emb,
                                                 token_mask_len, p_ahi, p_alo);
        run_bf3(p_whi + wooff, p_wlo + wooff, nullptr, p_h, NROWS, DD, DD, 1);

        rmsnorm_bf_k<<<NROWS, 256>>>(p_h, ffn_norm_w + i*DD, p_ahi, p_alo);
        run_bf3(p_whi + w13off, p_wlo + w13off, nullptr, p_f, NROWS, 8192, DD, 0);

        const int nf4 = (int)((size_t)NROWS * DFF / 4);
        silu_split_k<<<(nf4 + 255) / 256, 256>>>(p_f, p_ahi, p_alo, nf4);

        run_bf3(p_whi + w2off, p_wlo + w2off, nullptr, p_h, NROWS, DD, DFF, 1);
    }

    // 4) Final norm + output head
    rmsnorm_final_bf_k<<<OUTROWS, 256>>>(p_h, final_norm_w, p_ahi, p_alo);
    run_bf3(p_whi + OFF_OUT, p_wlo + OFF_OUT, out_b, (float*)d_out, OUTROWS, NVOC, DD, 0);
}

// round 13
// speedup vs baseline: 1.1216x; 1.1216x over previous
#include <cuda_runtime.h>
#include <cuda_bf16.h>
#include <math.h>
#include <stdint.h>

// Problem constants
#define BB    2
#define LL    1024
#define DD    1024
#define HH    16
#define FDIM  512
#define NLAY  4
#define NVOC  5000
#define DFF   4096
#define SS    1026          // L + 2
#define DHD   64
#define NROWS (BB*SS)       // 2052
#define OUTROWS (BB*(SS-1)) // 2050
#define NEGC  (-1000000000.0f)
#define PADS  1088          // padded S for idx tiles (17*64)

// Weight pool offsets (elements)
#define OFF_PROJ 0ULL
#define OFF_QKV  524288ULL          // stride/layer 3145728
#define OFF_WO   13107200ULL        // stride/layer 1048576
#define OFF_W13  17301504ULL        // stride/layer 8388608
#define OFF_W2   50855936ULL        // stride/layer 4194304
#define OFF_OUT  67633152ULL
#define WPOOL    72753152ULL

// ---------------------------------------------------------------------------
// Device scratch
// ---------------------------------------------------------------------------
__device__ float g_h[NROWS*DD];
__device__ float g_f[(size_t)NROWS*8192];        // W13 out + proj temp
__device__ unsigned char g_idxp[(size_t)BB*PADS*PADS];

__device__ __nv_bfloat16 g_whi[WPOOL];
__device__ __nv_bfloat16 g_wlo[WPOOL];
__device__ __nv_bfloat16 g_ahi[NROWS*DFF];       // A-operand hi
__device__ __nv_bfloat16 g_alo[NROWS*DFF];       // A-operand lo
__device__ __nv_bfloat16 g_qkvhi[(size_t)NROWS*3072];
__device__ __nv_bfloat16 g_qkvlo[(size_t)NROWS*3072];

// ---------------------------------------------------------------------------
// helpers
// ---------------------------------------------------------------------------
__device__ __forceinline__ void split1(float v, __nv_bfloat16& h, __nv_bfloat16& l) {
    h = __float2bfloat16(v);
    l = __float2bfloat16(v - __bfloat162float(h));
}
__device__ __forceinline__ uint32_t pack_bf2(__nv_bfloat16 x, __nv_bfloat16 y) {
    unsigned short a = *(unsigned short*)&x;
    unsigned short b = *(unsigned short*)&y;
    return (uint32_t)a | ((uint32_t)b << 16);
}
__device__ __forceinline__ void cp_async16(uint32_t smem_addr, const void* gptr, int src_size) {
    asm volatile("cp.async.cg.shared.global [%0], [%1], 16, %2;\n"
                 :: "r"(smem_addr), "l"(gptr), "r"(src_size));
}
__device__ __forceinline__ void cp_commit() { asm volatile("cp.async.commit_group;\n"); }
__device__ __forceinline__ void cp_wait0()  { asm volatile("cp.async.wait_group 0;\n"); }

__device__ __forceinline__ void ldsm_x4(uint32_t& r0, uint32_t& r1, uint32_t& r2, uint32_t& r3,
                                        uint32_t addr) {
    asm volatile("ldmatrix.sync.aligned.m8n8.x4.shared.b16 {%0,%1,%2,%3}, [%4];\n"
                 : "=r"(r0), "=r"(r1), "=r"(r2), "=r"(r3) : "r"(addr));
}
__device__ __forceinline__ void ldsm_x4t(uint32_t& r0, uint32_t& r1, uint32_t& r2, uint32_t& r3,
                                         uint32_t addr) {
    asm volatile("ldmatrix.sync.aligned.m8n8.x4.trans.shared.b16 {%0,%1,%2,%3}, [%4];\n"
                 : "=r"(r0), "=r"(r1), "=r"(r2), "=r"(r3) : "r"(addr));
}
__device__ __forceinline__ void mma16816(float* d,
    uint32_t a0, uint32_t a1, uint32_t a2, uint32_t a3, uint32_t b0, uint32_t b1)
{
    asm volatile("mma.sync.aligned.m16n8k16.row.col.f32.bf16.bf16.f32 "
        "{%0,%1,%2,%3}, {%4,%5,%6,%7}, {%8,%9}, {%0,%1,%2,%3};\n"
        : "+f"(d[0]), "+f"(d[1]), "+f"(d[2]), "+f"(d[3])
        : "r"(a0), "r"(a1), "r"(a2), "r"(a3), "r"(b0), "r"(b1));
}

// ---------------------------------------------------------------------------
// fp32 -> (hi, lo) split kernels
// ---------------------------------------------------------------------------
__global__ void split_k(const float* __restrict__ x, __nv_bfloat16* __restrict__ hi,
                        __nv_bfloat16* __restrict__ lo, int n4)
{
    int i = blockIdx.x * 256 + threadIdx.x;
    if (i >= n4) return;
    float4 v = ((const float4*)x)[i];
    __nv_bfloat16 h0,h1,h2,h3,l0,l1,l2,l3;
    split1(v.x,h0,l0); split1(v.y,h1,l1); split1(v.z,h2,l2); split1(v.w,h3,l3);
    __nv_bfloat162 a; a.x=h0; a.y=h1;  __nv_bfloat162 b; b.x=h2; b.y=h3;
    __nv_bfloat162 c; c.x=l0; c.y=l1;  __nv_bfloat162 d; d.x=l2; d.y=l3;
    ((__nv_bfloat162*)hi)[2*i] = a; ((__nv_bfloat162*)hi)[2*i+1] = b;
    ((__nv_bfloat162*)lo)[2*i] = c; ((__nv_bfloat162*)lo)[2*i+1] = d;
}

// pack [wq|wk|wv] along N into pool (per layer)
__global__ void pack_qkv_k(const float* __restrict__ wq, const float* __restrict__ wk,
                           const float* __restrict__ wv, int layer)
{
    const int n4 = DD * 3072 / 4;
    int i = blockIdx.x * 256 + threadIdx.x;
    if (i >= n4) return;
    size_t e = (size_t)i * 4;
    int k = (int)(e / 3072), j = (int)(e % 3072);
    const float* src;
    if (j < 1024)      src = wq + (size_t)layer*DD*DD + (size_t)k*DD + j;
    else if (j < 2048) src = wk + (size_t)layer*DD*DD + (size_t)k*DD + (j - 1024);
    else               src = wv + (size_t)layer*DD*DD + (size_t)k*DD + (j - 2048);
    float4 v = *(const float4*)src;
    size_t off = OFF_QKV + (size_t)layer * 3145728ULL + e;
    __nv_bfloat16 h0,h1,h2,h3,l0,l1,l2,l3;
    split1(v.x,h0,l0); split1(v.y,h1,l1); split1(v.z,h2,l2); split1(v.w,h3,l3);
    g_whi[off]=h0; g_whi[off+1]=h1; g_whi[off+2]=h2; g_whi[off+3]=h3;
    g_wlo[off]=l0; g_wlo[off+1]=l1; g_wlo[off+2]=l2; g_wlo[off+3]=l3;
}

// pack [w1|w3] along N into pool (per layer)
__global__ void pack_w13_k(const float* __restrict__ w1, const float* __restrict__ w3,
                           int layer)
{
    const int n4 = DD * 8192 / 4;
    int i = blockIdx.x * 256 + threadIdx.x;
    if (i >= n4) return;
    size_t e = (size_t)i * 4;
    int k = (int)(e / 8192), j = (int)(e % 8192);
    const float* src;
    if (j < 4096) src = w1 + (size_t)layer*DD*DFF + (size_t)k*DFF + j;
    else          src = w3 + (size_t)layer*DD*DFF + (size_t)k*DFF + (j - 4096);
    float4 v = *(const float4*)src;
    size_t off = OFF_W13 + (size_t)layer * 8388608ULL + e;
    __nv_bfloat16 h0,h1,h2,h3,l0,l1,l2,l3;
    split1(v.x,h0,l0); split1(v.y,h1,l1); split1(v.z,h2,l2); split1(v.w,h3,l3);
    g_whi[off]=h0; g_whi[off+1]=h1; g_whi[off+2]=h2; g_whi[off+3]=h3;
    g_wlo[off]=l0; g_wlo[off+1]=l1; g_wlo[off+2]=l2; g_wlo[off+3]=l3;
}

// ---------------------------------------------------------------------------
// bf16x3 GEMM, single K sweep, 3 MMA passes per BK=32 chunk:
//   C (+)= Ahi@Bhi + Alo@Bhi + Ahi@Blo
// MTILE x 128 tile, 256 threads.
//   MTILE=128: warps 2(M)x4(N), warp tile 64x32 (NI=4)
//   MTILE=256: warps 4(M)x2(N), warp tile 64x64 (NI=8)
// mode: 0 = C=f32 (+bias), 1 = C accumulate, 2 = bf16 hi/lo split out
// ---------------------------------------------------------------------------
template<int MTILE>
__global__ void __launch_bounds__(256) gemm3_t(
    const __nv_bfloat16* __restrict__ Ahi, const __nv_bfloat16* __restrict__ Alo,
    const __nv_bfloat16* __restrict__ Bhi, const __nv_bfloat16* __restrict__ Blo,
    const float* __restrict__ bias, float* __restrict__ C,
    __nv_bfloat16* __restrict__ Chi, __nv_bfloat16* __restrict__ Clo,
    int M, int N, int K, int mode)
{
    constexpr int NW = (MTILE == 128) ? 4 : 2;   // N-warps
    constexpr int NI = (128 / NW) / 8;           // 4 or 8 n-frags per warp
    constexpr int AT = MTILE * 40;               // A stage elems

    extern __shared__ __align__(16) char dyn[];
    __nv_bfloat16* sAhi = (__nv_bfloat16*)dyn;           // [2][MTILE][40]
    __nv_bfloat16* sAlo = sAhi + 2 * AT;
    __nv_bfloat16* sBhi = sAlo + 2 * AT;                 // [2][32][136]
    __nv_bfloat16* sBlo = sBhi + 2 * 32 * 136;

    const int tid  = threadIdx.x;
    const int lane = tid & 31;
    const int wid  = tid >> 5;
    const int wm   = (wid / NW) * 64;
    const int wn   = (wid % NW) * (NI * 8);
    const int brow = blockIdx.y * MTILE;
    const int bcol = blockIdx.x * 128;

    float acc[4][NI][4];
#pragma unroll
    for (int mi = 0; mi < 4; mi++)
#pragma unroll
        for (int ni = 0; ni < NI; ni++)
#pragma unroll
            for (int r = 0; r < 4; r++) acc[mi][ni][r] = 0.f;

    const uint32_t aAhi = (uint32_t)__cvta_generic_to_shared(sAhi);
    const uint32_t aAlo = (uint32_t)__cvta_generic_to_shared(sAlo);
    const uint32_t aBhi = (uint32_t)__cvta_generic_to_shared(sBhi);
    const uint32_t aBlo = (uint32_t)__cvta_generic_to_shared(sBlo);

    const int nchunks = K >> 5;

    auto load_chunk = [&](int b, int t) {
        const int k0 = t << 5;
#pragma unroll
        for (int c = 0; c < MTILE / 64; c++) {
            const int cid = tid + (c << 8);
            const int row = cid >> 2, chk = cid & 3;
            const int grow = brow + row;
            const int sz = (grow < M) ? 16 : 0;
            const size_t goff = (size_t)(sz ? grow : 0) * K + k0 + chk * 8;
            const uint32_t doff = (uint32_t)(((b * MTILE + row) * 40 + chk * 8) << 1);
            cp_async16(aAhi + doff, Ahi + goff, sz);
            cp_async16(aAlo + doff, Alo + goff, sz);
        }
#pragma unroll
        for (int c = 0; c < 2; c++) {
            const int cid = tid + (c << 8);
            const int row = cid >> 4, chk = cid & 15;
            const int gcol = bcol + chk * 8;
            const int sz = (gcol + 8 <= N) ? 16 : 0;
            const size_t goff = (size_t)(k0 + row) * N + (sz ? gcol : 0);
            const uint32_t doff = (uint32_t)(((b * 32 + row) * 136 + chk * 8) << 1);
            cp_async16(aBhi + doff, Bhi + goff, sz);
            cp_async16(aBlo + doff, Blo + goff, sz);
        }
    };

    load_chunk(0, 0);
    cp_commit();

    const int a_row = (lane & 15);
    const int a_col = (lane >> 4) * 8;

    for (int t = 0; t < nchunks; ++t) {
        cp_wait0();
        __syncthreads();
        if (t + 1 < nchunks) { load_chunk((t + 1) & 1, t + 1); cp_commit(); }
        const int buf = t & 1;

#pragma unroll
        for (int ks = 0; ks < 32; ks += 16) {
            uint32_t afh[4][4], bfh[NI][2];
#pragma unroll
            for (int mi = 0; mi < 4; mi++) {
                const uint32_t off =
                    (uint32_t)(((buf * MTILE + wm + mi * 16 + a_row) * 40 + ks + a_col) << 1);
                ldsm_x4(afh[mi][0], afh[mi][1], afh[mi][2], afh[mi][3], aAhi + off);
            }
#pragma unroll
            for (int pr = 0; pr < NI / 2; pr++) {
                const uint32_t off =
                    (uint32_t)(((buf * 32 + ks + a_row) * 136 + wn + pr * 16 + a_col) << 1);
                ldsm_x4t(bfh[pr*2][0], bfh[pr*2][1], bfh[pr*2+1][0], bfh[pr*2+1][1], aBhi + off);
            }
            // pass 1: Ahi x Bhi
#pragma unroll
            for (int mi = 0; mi < 4; mi++)
#pragma unroll
                for (int ni = 0; ni < NI; ni++)
                    mma16816(acc[mi][ni], afh[mi][0], afh[mi][1], afh[mi][2], afh[mi][3],
                             bfh[ni][0], bfh[ni][1]);
            // pass 2: Alo x Bhi
#pragma unroll
            for (int mi = 0; mi < 4; mi++) {
                uint32_t t4[4];
                const uint32_t off =
                    (uint32_t)(((buf * MTILE + wm + mi * 16 + a_row) * 40 + ks + a_col) << 1);
                ldsm_x4(t4[0], t4[1], t4[2], t4[3], aAlo + off);
#pragma unroll
                for (int ni = 0; ni < NI; ni++)
                    mma16816(acc[mi][ni], t4[0], t4[1], t4[2], t4[3], bfh[ni][0], bfh[ni][1]);
            }
            // pass 3: Ahi x Blo
#pragma unroll
            for (int pr = 0; pr < NI / 2; pr++) {
                uint32_t t4[4];
                const uint32_t off =
                    (uint32_t)(((buf * 32 + ks + a_row) * 136 + wn + pr * 16 + a_col) << 1);
                ldsm_x4t(t4[0], t4[1], t4[2], t4[3], aBlo + off);
#pragma unroll
                for (int mi = 0; mi < 4; mi++) {
                    mma16816(acc[mi][pr*2],   afh[mi][0], afh[mi][1], afh[mi][2], afh[mi][3],
                             t4[0], t4[1]);
                    mma16816(acc[mi][pr*2+1], afh[mi][0], afh[mi][1], afh[mi][2], afh[mi][3],
                             t4[2], t4[3]);
                }
            }
        }
        __syncthreads();
    }

    // Epilogue
#pragma unroll
    for (int mi = 0; mi < 4; mi++) {
        const int r0 = brow + wm + mi * 16 + (lane >> 2);
#pragma unroll
        for (int ni = 0; ni < NI; ni++) {
            const int c0 = bcol + wn + ni * 8 + (lane & 3) * 2;
#pragma unroll
            for (int half = 0; half < 2; half++) {
                const int r = r0 + half * 8;
                if (r >= M) continue;
#pragma unroll
                for (int cc = 0; cc < 2; cc++) {
                    const int c = c0 + cc;
                    if (c >= N) continue;
                    float v = acc[mi][ni][half * 2 + cc];
                    if (mode == 2) {
                        __nv_bfloat16 hv, lv;
                        split1(v, hv, lv);
                        Chi[(size_t)r * N + c] = hv;
                        Clo[(size_t)r * N + c] = lv;
                    } else {
                        if (bias) v += bias[c];
                        if (mode == 1) v += C[(size_t)r * N + c];
                        C[(size_t)r * N + c] = v;
                    }
                }
            }
        }
    }
}

// ---------------------------------------------------------------------------
// Fused flash attention. block = 128 thr (4 warps, 16 q-rows each).
// grid = (17 qtiles, B*H). Inputs: packed QKV hi/lo. Output att hi/lo.
// ---------------------------------------------------------------------------
__global__ void __launch_bounds__(128) flash_k(
    const __nv_bfloat16* __restrict__ qkvhi, const __nv_bfloat16* __restrict__ qkvlo,
    const float* __restrict__ spd_emb, const int* __restrict__ mask_len,
    __nv_bfloat16* __restrict__ ohi, __nv_bfloat16* __restrict__ olo)
{
    extern __shared__ __align__(16) char sm[];
    __nv_bfloat16* sKhi = (__nv_bfloat16*)sm;        // [64][72]
    __nv_bfloat16* sKlo = sKhi + 64*72;
    __nv_bfloat16* sVhi = sKlo + 64*72;
    __nv_bfloat16* sVlo = sVhi + 64*72;
    __nv_bfloat16* sQhi = sVlo + 64*72;
    __nv_bfloat16* sQlo = sQhi + 64*72;
    unsigned char* sIdx = (unsigned char*)(sQlo + 64*72); // [64][64]
    float* sB = (float*)(sIdx + 64*64);              // [32]

    const int tid = threadIdx.x, lane = tid & 31, wid = tid >> 5;
    const int wr = wid * 16;
    const int bh = blockIdx.y, b = bh >> 4, h = bh & 15;
    const int q0 = blockIdx.x * 64;
    const int vlen = mask_len[b] + 2;

    if (tid < 32) sB[tid] = spd_emb[tid * HH + h];

    const uint32_t sKhi_a = (uint32_t)__cvta_generic_to_shared(sKhi);
    const uint32_t sKlo_a = (uint32_t)__cvta_generic_to_shared(sKlo);
    const uint32_t sVhi_a = (uint32_t)__cvta_generic_to_shared(sVhi);
    const uint32_t sVlo_a = (uint32_t)__cvta_generic_to_shared(sVlo);
    const uint32_t sQhi_a = (uint32_t)__cvta_generic_to_shared(sQhi);
    const uint32_t sQlo_a = (uint32_t)__cvta_generic_to_shared(sQlo);
    const uint32_t sIdx_a = (uint32_t)__cvta_generic_to_shared(sIdx);

    // Load Q tile (hi/lo)
#pragma unroll
    for (int c = 0; c < 4; c++) {
        const int cid = tid + c * 128;
        const int row = cid >> 3, chk = cid & 7;
        const int gq = q0 + row;
        size_t base = ((size_t)(b * SS + gq)) * 3072 + h * 64 + chk * 8;
        int sz = (gq < SS) ? 16 : 0;
        const __nv_bfloat16* sh = (gq < SS) ? qkvhi + base : qkvhi;
        const __nv_bfloat16* sl = (gq < SS) ? qkvlo + base : qkvlo;
        cp_async16(sQhi_a + (uint32_t)((row * 72 + chk * 8) << 1), sh, sz);
        cp_async16(sQlo_a + (uint32_t)((row * 72 + chk * 8) << 1), sl, sz);
    }
    cp_commit(); cp_wait0(); __syncthreads();

    uint32_t qfh[4][4], qfl[4][4];
#pragma unroll
    for (int c = 0; c < 4; c++) {
        uint32_t off = (uint32_t)((((wr + (lane & 15)) * 72) + c * 16 + ((lane >> 4) << 3)) << 1);
        ldsm_x4(qfh[c][0], qfh[c][1], qfh[c][2], qfh[c][3], sQhi_a + off);
        ldsm_x4(qfl[c][0], qfl[c][1], qfl[c][2], qfl[c][3], sQlo_a + off);
    }

    float m_a = -1e30f, m_b = -1e30f, l_a = 0.f, l_b = 0.f;
    float O[8][4];
#pragma unroll
    for (int nt = 0; nt < 8; nt++)
#pragma unroll
        for (int j = 0; j < 4; j++) O[nt][j] = 0.f;

    const int qa_l = wr + (lane >> 2);
    const int qb_l = qa_l + 8;
    const int qga = q0 + qa_l, qgb = q0 + qb_l;
    const float mka = (qga < vlen) ? 0.f : NEGC;
    const float mkb = (qgb < vlen) ? 0.f : NEGC;
    const int kc_base = (lane & 3) * 2;

    for (int kt = 0; kt < 17; kt++) {
        const int k0 = kt * 64;
        __syncthreads();
        // load K/V hi/lo tiles + idx tile
#pragma unroll
        for (int c = 0; c < 4; c++) {
            const int cid = tid + c * 128;
            const int row = cid >> 3, chk = cid & 7;
            const int gk = k0 + row;
            size_t base = ((size_t)(b * SS + gk)) * 3072 + h * 64 + chk * 8;
            int sz = (gk < SS) ? 16 : 0;
            const __nv_bfloat16* kh = (gk < SS) ? qkvhi + base + 1024 : qkvhi;
            const __nv_bfloat16* kl = (gk < SS) ? qkvlo + base + 1024 : qkvlo;
            const __nv_bfloat16* vh = (gk < SS) ? qkvhi + base + 2048 : qkvhi;
            const __nv_bfloat16* vl = (gk < SS) ? qkvlo + base + 2048 : qkvlo;
            uint32_t doff = (uint32_t)((row * 72 + chk * 8) << 1);
            cp_async16(sKhi_a + doff, kh, sz);
            cp_async16(sKlo_a + doff, kl, sz);
            cp_async16(sVhi_a + doff, vh, sz);
            cp_async16(sVlo_a + doff, vl, sz);
        }
#pragma unroll
        for (int c = 0; c < 2; c++) {
            const int cid = tid + c * 128;
            const int row = cid >> 2, chk = cid & 3;
            const unsigned char* src = g_idxp + ((size_t)b * PADS + q0 + row) * PADS + k0 + chk * 16;
            cp_async16(sIdx_a + (uint32_t)(row * 64 + chk * 16), src, 16);
        }
        cp_commit(); cp_wait0(); __syncthreads();

        // S = Q K^T (3-term)
        float s[8][4];
#pragma unroll
        for (int nt = 0; nt < 8; nt++)
#pragma unroll
            for (int j = 0; j < 4; j++) s[nt][j] = 0.f;

#pragma unroll
        for (int c = 0; c < 4; c++) {
#pragma unroll
            for (int p = 0; p < 4; p++) {
                uint32_t r0, r1, r2, r3;
                uint32_t off = (uint32_t)((((p * 16 + (lane & 15)) * 72) + c * 16 + ((lane >> 4) << 3)) << 1);
                ldsm_x4(r0, r1, r2, r3, sKhi_a + off);
                mma16816(s[2*p],   qfh[c][0], qfh[c][1], qfh[c][2], qfh[c][3], r0, r2);
                mma16816(s[2*p+1], qfh[c][0], qfh[c][1], qfh[c][2], qfh[c][3], r1, r3);
                mma16816(s[2*p],   qfl[c][0], qfl[c][1], qfl[c][2], qfl[c][3], r0, r2);
                mma16816(s[2*p+1], qfl[c][0], qfl[c][1], qfl[c][2], qfl[c][3], r1, r3);
                ldsm_x4(r0, r1, r2, r3, sKlo_a + off);
                mma16816(s[2*p],   qfh[c][0], qfh[c][1], qfh[c][2], qfh[c][3], r0, r2);
                mma16816(s[2*p+1], qfh[c][0], qfh[c][1], qfh[c][2], qfh[c][3], r1, r3);
            }
        }

        // scale + bias + mask
        float pmax_a = -1e30f, pmax_b = -1e30f;
#pragma unroll
        for (int nt = 0; nt < 8; nt++) {
            const int colbase = nt * 8 + kc_base;
#pragma unroll
            for (int j = 0; j < 4; j++) {
                const int kc = colbase + (j & 1);
                const int qr = (j < 2) ? qa_l : qb_l;
                const float bias = sB[sIdx[qr * 64 + kc]];
                float v = (s[nt][j] * 0.125f + bias) + ((j < 2) ? mka : mkb);
                if (k0 + kc >= SS) v = -1e30f;
                s[nt][j] = v;
                if (j < 2) pmax_a = fmaxf(pmax_a, v);
                else       pmax_b = fmaxf(pmax_b, v);
            }
        }
        pmax_a = fmaxf(pmax_a, __shfl_xor_sync(0xffffffff, pmax_a, 1));
        pmax_a = fmaxf(pmax_a, __shfl_xor_sync(0xffffffff, pmax_a, 2));
        pmax_b = fmaxf(pmax_b, __shfl_xor_sync(0xffffffff, pmax_b, 1));
        pmax_b = fmaxf(pmax_b, __shfl_xor_sync(0xffffffff, pmax_b, 2));

        const float mna = fmaxf(m_a, pmax_a), mnb = fmaxf(m_b, pmax_b);
        const float ca = __expf(m_a - mna), cb = __expf(m_b - mnb);
        float suma = 0.f, sumb = 0.f;
#pragma unroll
        for (int nt = 0; nt < 8; nt++) {
#pragma unroll
            for (int j = 0; j < 4; j++) {
                float e = __expf(s[nt][j] - ((j < 2) ? mna : mnb));
                s[nt][j] = e;
                if (j < 2) suma += e; else sumb += e;
            }
        }
        suma += __shfl_xor_sync(0xffffffff, suma, 1);
        suma += __shfl_xor_sync(0xffffffff, suma, 2);
        sumb += __shfl_xor_sync(0xffffffff, sumb, 1);
        sumb += __shfl_xor_sync(0xffffffff, sumb, 2);
        l_a = l_a * ca + suma; m_a = mna;
        l_b = l_b * cb + sumb; m_b = mnb;
#pragma unroll
        for (int nt = 0; nt < 8; nt++) {
            O[nt][0] *= ca; O[nt][1] *= ca;
            O[nt][2] *= cb; O[nt][3] *= cb;
        }

        // PV (3-term): P from accumulators -> a-frags
#pragma unroll
        for (int c = 0; c < 4; c++) {
            __nv_bfloat16 h00,h01,h02,h03,h10,h11,h12,h13;
            __nv_bfloat16 l00,l01,l02,l03,l10,l11,l12,l13;
            split1(s[2*c][0], h00, l00); split1(s[2*c][1], h01, l01);
            split1(s[2*c][2], h02, l02); split1(s[2*c][3], h03, l03);
            split1(s[2*c+1][0], h10, l10); split1(s[2*c+1][1], h11, l11);
            split1(s[2*c+1][2], h12, l12); split1(s[2*c+1][3], h13, l13);
            uint32_t pa0 = pack_bf2(h00, h01), pa1 = pack_bf2(h02, h03);
            uint32_t pa2 = pack_bf2(h10, h11), pa3 = pack_bf2(h12, h13);
            uint32_t pl0 = pack_bf2(l00, l01), pl1 = pack_bf2(l02, l03);
            uint32_t pl2 = pack_bf2(l10, l11), pl3 = pack_bf2(l12, l13);
#pragma unroll
            for (int dp = 0; dp < 4; dp++) {
                uint32_t r0, r1, r2, r3;
                uint32_t off = (uint32_t)((((c * 16 + (lane & 15)) * 72) + dp * 16 + ((lane >> 4) << 3)) << 1);
                ldsm_x4t(r0, r1, r2, r3, sVhi_a + off);
                mma16816(O[2*dp],   pa0, pa1, pa2, pa3, r0, r1);
                mma16816(O[2*dp+1], pa0, pa1, pa2, pa3, r2, r3);
                mma16816(O[2*dp],   pl0, pl1, pl2, pl3, r0, r1);
                mma16816(O[2*dp+1], pl0, pl1, pl2, pl3, r2, r3);
                ldsm_x4t(r0, r1, r2, r3, sVlo_a + off);
                mma16816(O[2*dp],   pa0, pa1, pa2, pa3, r0, r1);
                mma16816(O[2*dp+1], pa0, pa1, pa2, pa3, r2, r3);
            }
        }
    }

    // epilogue: normalize + split-store
    const float ia = 1.f / l_a, ib = 1.f / l_b;
#pragma unroll
    for (int nt = 0; nt < 8; nt++) {
#pragma unroll
        for (int j = 0; j < 4; j++) {
            const int q = (j < 2) ? qga : qgb;
            if (q >= SS) continue;
            const int d = h * 64 + nt * 8 + kc_base + (j & 1);
            float v = O[nt][j] * ((j < 2) ? ia : ib);
            __nv_bfloat16 hv, lv;
            split1(v, hv, lv);
            const size_t off = ((size_t)(b * SS + q)) * DD + d;
            ohi[off] = hv; olo[off] = lv;
        }
    }
}

// ---------------------------------------------------------------------------
// Embedding assembly
// ---------------------------------------------------------------------------
__global__ void embed_k(
    const float* __restrict__ proj, const float* __restrict__ graph,
    const float* __restrict__ sos,  const float* __restrict__ node_emb,
    const float* __restrict__ type_emb, const float* __restrict__ pos_emb,
    const int*   __restrict__ sub)
{
    const int s = blockIdx.x;
    const int b = blockIdx.y;
    const int d = threadIdx.x * 4;

    float4 pos = *(const float4*)(pos_emb + (size_t)s * DD + d);
    float4 o;
    if (s == 0) {
        float4 g = *(const float4*)(graph + (size_t)b * DD + d);
        float4 t1 = *(const float4*)(type_emb + DD + d);
        o.x = g.x + t1.x + pos.x; o.y = g.y + t1.y + pos.y;
        o.z = g.z + t1.z + pos.z; o.w = g.w + t1.w + pos.w;
    } else {
        const int t = s - 1;
        float4 base;
        int nid;
        if (t == 0) {
            base = *(const float4*)(sos + d);
            nid = 0;
        } else {
            base = *(const float4*)(proj + ((size_t)b * LL + (t-1)) * DD + d);
            nid = sub[b * LL + (t-1)];
        }
        float4 ne = *(const float4*)(node_emb + (size_t)nid * DD + d);
        float4 t0 = *(const float4*)(type_emb + d);
        o.x = base.x + ne.x + t0.x + pos.x;
        o.y = base.y + ne.y + t0.y + pos.y;
        o.z = base.z + ne.z + t0.z + pos.z;
        o.w = base.w + ne.w + t0.w + pos.w;
    }
    *(float4*)(g_h + ((size_t)b * SS + s) * DD + d) = o;
}

// ---------------------------------------------------------------------------
// spd bias index precompute into padded [PADS][PADS] (OOB -> 31)
// ---------------------------------------------------------------------------
__global__ void spdidx_k(const int* __restrict__ spd)
{
    const int qk = blockIdx.x * 256 + threadIdx.x;
    const int b  = blockIdx.y;
    if (qk >= PADS * PADS) return;
    const int q = qk / PADS, k = qk % PADS;
    int idx;
    if (q >= SS || k >= SS) idx = 31;
    else if (q >= 2 && k >= 2) {
        idx = spd[((size_t)b * LL + (q-2)) * LL + (k-2)];
        if (idx < 0) idx = 0;
        if (idx > 31) idx = 31;
    } else {
        idx = (q == k) ? 0 : 31;
    }
    g_idxp[(size_t)b * PADS * PADS + qk] = (unsigned char)idx;
}

// ---------------------------------------------------------------------------
// RMSNorm -> bf16 hi/lo
// ---------------------------------------------------------------------------
__device__ __forceinline__ float block_reduce_sum(float v, float* red) {
    const int tid = threadIdx.x;
    red[tid] = v; __syncthreads();
    for (int s = 128; s > 0; s >>= 1) {
        if (tid < s) red[tid] += red[tid + s];
        __syncthreads();
    }
    float r = red[0]; __syncthreads();
    return r;
}

__global__ void rmsnorm_bf_k(const float* __restrict__ h, const float* __restrict__ w,
                             __nv_bfloat16* __restrict__ hi, __nv_bfloat16* __restrict__ lo)
{
    __shared__ float red[256];
    const int row = blockIdx.x;
    const int tid = threadIdx.x;
    const float* x = h + (size_t)row * DD;
    float4 xv = *(const float4*)(x + tid * 4);
    float ss = xv.x*xv.x + xv.y*xv.y + xv.z*xv.z + xv.w*xv.w;
    float tot = block_reduce_sum(ss, red);
    float inv = rsqrtf(tot / (float)DD + 1e-6f);
    float4 wv = *(const float4*)(w + tid * 4);
    float o0 = xv.x*inv*wv.x, o1 = xv.y*inv*wv.y, o2 = xv.z*inv*wv.z, o3 = xv.w*inv*wv.w;
    __nv_bfloat16 h0,h1,h2,h3,l0,l1,l2,l3;
    split1(o0,h0,l0); split1(o1,h1,l1); split1(o2,h2,l2); split1(o3,h3,l3);
    const size_t base = (size_t)row * DD + tid * 4;
    hi[base+0]=h0; hi[base+1]=h1; hi[base+2]=h2; hi[base+3]=h3;
    lo[base+0]=l0; lo[base+1]=l1; lo[base+2]=l2; lo[base+3]=l3;
}

__global__ void rmsnorm_final_bf_k(const float* __restrict__ h, const float* __restrict__ w,
                                   __nv_bfloat16* __restrict__ hi, __nv_bfloat16* __restrict__ lo)
{
    __shared__ float red[256];
    const int r = blockIdx.x;
    const int b = r / (SS - 1);
    const int t = r % (SS - 1);
    const int src = b * SS + 1 + t;
    const int tid = threadIdx.x;
    const float* x = h + (size_t)src * DD;
    float4 xv = *(const float4*)(x + tid * 4);
    float ss = xv.x*xv.x + xv.y*xv.y + xv.z*xv.z + xv.w*xv.w;
    float tot = block_reduce_sum(ss, red);
    float inv = rsqrtf(tot / (float)DD + 1e-6f);
    float4 wv = *(const float4*)(w + tid * 4);
    float o0 = xv.x*inv*wv.x, o1 = xv.y*inv*wv.y, o2 = xv.z*inv*wv.z, o3 = xv.w*inv*wv.w;
    __nv_bfloat16 h0,h1,h2,h3,l0,l1,l2,l3;
    split1(o0,h0,l0); split1(o1,h1,l1); split1(o2,h2,l2); split1(o3,h3,l3);
    const size_t base = (size_t)r * DD + tid * 4;
    hi[base+0]=h0; hi[base+1]=h1; hi[base+2]=h2; hi[base+3]=h3;
    lo[base+0]=l0; lo[base+1]=l1; lo[base+2]=l2; lo[base+3]=l3;
}

// ---------------------------------------------------------------------------
// SwiGLU gate from packed g_f [NROWS][8192] -> bf16 hi/lo [NROWS][4096]
// ---------------------------------------------------------------------------
__global__ void silu_split_k(const float* __restrict__ f,
                             __nv_bfloat16* __restrict__ hi, __nv_bfloat16* __restrict__ lo,
                             int n4)
{
    int i = blockIdx.x * 256 + threadIdx.x;
    if (i >= n4) return;
    size_t e = (size_t)i * 4;
    int r = (int)(e >> 12);          // /4096
    int c = (int)(e & 4095);
    float4 a = *(const float4*)(f + (size_t)r * 8192 + c);
    float4 g = *(const float4*)(f + (size_t)r * 8192 + 4096 + c);
    float o0 = (a.x / (1.f + __expf(-a.x))) * g.x;
    float o1 = (a.y / (1.f + __expf(-a.y))) * g.y;
    float o2 = (a.z / (1.f + __expf(-a.z))) * g.z;
    float o3 = (a.w / (1.f + __expf(-a.w))) * g.w;
    __nv_bfloat16 h0,h1,h2,h3,l0,l1,l2,l3;
    split1(o0,h0,l0); split1(o1,h1,l1); split1(o2,h2,l2); split1(o3,h3,l3);
    hi[e+0]=h0; hi[e+1]=h1; hi[e+2]=h2; hi[e+3]=h3;
    lo[e+0]=l0; lo[e+1]=l1; lo[e+2]=l2; lo[e+3]=l3;
}

// ---------------------------------------------------------------------------
// Host orchestration
// ---------------------------------------------------------------------------
static __nv_bfloat16 *p_whi, *p_wlo, *p_ahi, *p_alo, *p_qkvhi, *p_qkvlo;

#define SMEM128 (2*(128*40 + 128*40)*2 + 2*(32*136 + 32*136)*2)   // 75776
#define SMEM256 (2*(256*40 + 256*40)*2 + 2*(32*136 + 32*136)*2)   // 116736

static inline void run_g3(const __nv_bfloat16* Bhi, const __nv_bfloat16* Blo,
                          const float* bias, float* C,
                          __nv_bfloat16* Chi, __nv_bfloat16* Clo,
                          int M, int N, int K, int mode)
{
    if (N >= 2048) {
        dim3 grid((N + 127) / 128, (M + 255) / 256);
        gemm3_t<256><<<grid, 256, SMEM256>>>(p_ahi, p_alo, Bhi, Blo, bias, C, Chi, Clo,
                                             M, N, K, mode);
    } else {
        dim3 grid((N + 127) / 128, (M + 127) / 128);
        gemm3_t<128><<<grid, 256, SMEM128>>>(p_ahi, p_alo, Bhi, Blo, bias, C, Chi, Clo,
                                             M, N, K, mode);
    }
}

extern "C" void kernel_launch(void* const* d_in, const int* in_sizes, int n_in,
                              void* d_out, int out_size)
{
    const float* graph_features = (const float*)d_in[0];
    const float* input_features = (const float*)d_in[1];
    const float* proj_W         = (const float*)d_in[2];
    const float* proj_b         = (const float*)d_in[3];
    const float* sos_token      = (const float*)d_in[4];
    const float* node_emb       = (const float*)d_in[5];
    const float* type_emb       = (const float*)d_in[6];
    const float* pos_emb        = (const float*)d_in[7];
    const float* spd_emb        = (const float*)d_in[8];
    const float* attn_norm_w    = (const float*)d_in[9];
    const float* wq             = (const float*)d_in[10];
    const float* wk             = (const float*)d_in[11];
    const float* wv             = (const float*)d_in[12];
    const float* wo             = (const float*)d_in[13];
    const float* ffn_norm_w     = (const float*)d_in[14];
    const float* w1             = (const float*)d_in[15];
    const float* w2             = (const float*)d_in[16];
    const float* w3             = (const float*)d_in[17];
    const float* final_norm_w   = (const float*)d_in[18];
    const float* out_W          = (const float*)d_in[19];
    const float* out_b          = (const float*)d_in[20];
    const int*   subnode_ids    = (const int*)d_in[21];
    const int*   token_mask_len = (const int*)d_in[22];
    const int*   spd_indices    = (const int*)d_in[23];

    float *p_h, *p_f;
    cudaGetSymbolAddress((void**)&p_h,   g_h);
    cudaGetSymbolAddress((void**)&p_f,   g_f);
    cudaGetSymbolAddress((void**)&p_whi, g_whi);
    cudaGetSymbolAddress((void**)&p_wlo, g_wlo);
    cudaGetSymbolAddress((void**)&p_ahi, g_ahi);
    cudaGetSymbolAddress((void**)&p_alo, g_alo);
    cudaGetSymbolAddress((void**)&p_qkvhi, g_qkvhi);
    cudaGetSymbolAddress((void**)&p_qkvlo, g_qkvlo);

    cudaFuncSetAttribute(flash_k, cudaFuncAttributeMaxDynamicSharedMemorySize, 59520);
    cudaFuncSetAttribute(gemm3_t<128>, cudaFuncAttributeMaxDynamicSharedMemorySize, SMEM128);
    cudaFuncSetAttribute(gemm3_t<256>, cudaFuncAttributeMaxDynamicSharedMemorySize, SMEM256);

    // 0) Weight splits/packs + spd idx
    auto splitw = [&](const float* src, size_t off, size_t count) {
        split_k<<<(unsigned)((count/4 + 255) / 256), 256>>>(src, p_whi + off, p_wlo + off,
                                                            (int)(count/4));
    };
    splitw(proj_W, OFF_PROJ, (size_t)FDIM*DD);
    for (int i = 0; i < NLAY; i++) {
        pack_qkv_k<<<(DD*3072/4 + 255)/256, 256>>>(wq, wk, wv, i);
        splitw(wo + (size_t)i*DD*DD, OFF_WO + (size_t)i*DD*DD, (size_t)DD*DD);
        pack_w13_k<<<(DD*8192/4 + 255)/256, 256>>>(w1, w3, i);
        splitw(w2 + (size_t)i*DFF*DD, OFF_W2 + (size_t)i*DFF*DD, (size_t)DFF*DD);
    }
    splitw(out_W, OFF_OUT, (size_t)DD*NVOC);
    spdidx_k<<<dim3((PADS*PADS + 255) / 256, BB), 256>>>(spd_indices);

    // 1) Input projection -> g_f (temp, row stride 1024)
    split_k<<<(unsigned)(((size_t)BB*LL*FDIM/4 + 255) / 256), 256>>>(
        input_features, p_ahi, p_alo, (int)((size_t)BB*LL*FDIM/4));
    run_g3(p_whi + OFF_PROJ, p_wlo + OFF_PROJ, proj_b, p_f, nullptr, nullptr,
           BB*LL, DD, FDIM, 0);

    // 2) Embedding assembly -> g_h
    embed_k<<<dim3(SS, BB), 256>>>(p_f, graph_features, sos_token,
                                   node_emb, type_emb, pos_emb, subnode_ids);

    // 3) Transformer layers
    for (int i = 0; i < NLAY; i++) {
        const size_t qkvoff = OFF_QKV + (size_t)i * 3145728ULL;
        const size_t wooff  = OFF_WO  + (size_t)i * 1048576ULL;
        const size_t w13off = OFF_W13 + (size_t)i * 8388608ULL;
        const size_t w2off  = OFF_W2  + (size_t)i * 4194304ULL;

        rmsnorm_bf_k<<<NROWS, 256>>>(p_h, attn_norm_w + i*DD, p_ahi, p_alo);
        run_g3(p_whi + qkvoff, p_wlo + qkvoff, nullptr, nullptr, p_qkvhi, p_qkvlo,
               NROWS, 3072, DD, 2);
        flash_k<<<dim3(17, BB*HH), 128, 59520>>>(p_qkvhi, p_qkvlo, spd_emb,
                                                 token_mask_len, p_ahi, p_alo);
        run_g3(p_whi + wooff, p_wlo + wooff, nullptr, p_h, nullptr, nullptr,
               NROWS, DD, DD, 1);

        rmsnorm_bf_k<<<NROWS, 256>>>(p_h, ffn_norm_w + i*DD, p_ahi, p_alo);
        run_g3(p_whi + w13off, p_wlo + w13off, nullptr, p_f, nullptr, nullptr,
               NROWS, 8192, DD, 0);

        const int nf4 = (int)((size_t)NROWS * DFF / 4);
        silu_split_k<<<(nf4 + 255) / 256, 256>>>(p_f, p_ahi, p_alo, nf4);

        run_g3(p_whi + w2off, p_wlo + w2off, nullptr, p_h, nullptr, nullptr,
               NROWS, DD, DFF, 1);
    }

    // 4) Final norm + output head
    rmsnorm_final_bf_k<<<OUTROWS, 256>>>(p_h, final_norm_w, p_ahi, p_alo);
    run_g3(p_whi + OFF_OUT, p_wlo + OFF_OUT, out_b, (float*)d_out, nullptr, nullptr,
           OUTROWS, NVOC, DD, 0);
}